// round 1
// baseline (speedup 1.0000x reference)
#include <cuda_runtime.h>

#define N 768
#define D 512
#define MAXP ((N * (N - 1)) / 2)
#define CBLOCKS 592
#define CTHREADS 256
#define NWARPS (CBLOCKS * CTHREADS / 32)   // 4736 warps

// Scratch (no allocations allowed in kernel_launch)
__device__ float g_mu[N * D];
__device__ float g_sig[N * D];
__device__ int2  g_pairs[MAXP];
__device__ float g_partials[NWARPS];
__device__ int   g_count;
__device__ int   g_is64;

__device__ __forceinline__ float fast_rcp(float x) {
    float r; asm("rcp.approx.f32 %0, %1;" : "=f"(r) : "f"(x)); return r;
}
__device__ __forceinline__ float fast_lg2(float x) {
    float r; asm("lg2.approx.f32 %0, %1;" : "=f"(r) : "f"(x)); return r;
}

// ---------------------------------------------------------------------------
// 1) Detect gty element width (int64 vs int32) + reset pair counter.
//    Reading the first 768 int32 words is safe for either layout.
//    If the buffer is int64 (values in [0,64)), every odd int32 word is 0.
// ---------------------------------------------------------------------------
__global__ void init_kernel(const void* gty) {
    __shared__ int odd_nonzero;
    if (threadIdx.x == 0) { odd_nonzero = 0; g_count = 0; }
    __syncthreads();
    const int* p = (const int*)gty;
    int v = p[threadIdx.x];
    if ((threadIdx.x & 1) && v != 0) atomicExch(&odd_nonzero, 1);
    __syncthreads();
    if (threadIdx.x == 0) g_is64 = odd_nonzero ? 0 : 1;
}

// ---------------------------------------------------------------------------
// 2) Per-row: L2-normalize mu_X, sig = exp(log_sigma_sq). One block per row.
// ---------------------------------------------------------------------------
__global__ void prep_kernel(const float* __restrict__ muX,
                            const float* __restrict__ lss) {
    int row = blockIdx.x;
    int t = threadIdx.x;            // 128 threads, 4 floats each
    const float4* src = (const float4*)(muX + (size_t)row * D);
    float4 v = src[t];
    float ss = v.x * v.x + v.y * v.y + v.z * v.z + v.w * v.w;
    #pragma unroll
    for (int o = 16; o; o >>= 1) ss += __shfl_xor_sync(0xFFFFFFFFu, ss, o);
    __shared__ float ws[4];
    if ((t & 31) == 0) ws[t >> 5] = ss;
    __syncthreads();
    float total = ws[0] + ws[1] + ws[2] + ws[3];
    float rn = 1.0f / fmaxf(sqrtf(total), 1e-12f);

    float4* dmu = (float4*)(g_mu + (size_t)row * D);
    dmu[t] = make_float4(v.x * rn, v.y * rn, v.z * rn, v.w * rn);

    const float4* lsrc = (const float4*)(lss + (size_t)row * D);
    float4 l = lsrc[t];
    float4* dsig = (float4*)(g_sig + (size_t)row * D);
    dsig[t] = make_float4(__expf(l.x), __expf(l.y), __expf(l.z), __expf(l.w));
}

// ---------------------------------------------------------------------------
// 3) Compact positive (same-class, i<j) pairs into g_pairs.
// ---------------------------------------------------------------------------
__global__ void pairs_kernel(const void* gty) {
    int idx = blockIdx.x * blockDim.x + threadIdx.x;
    if (idx >= N * N) return;
    int i = idx / N;
    int j = idx - i * N;
    if (j <= i) return;
    int ci, cj;
    if (g_is64) {
        const long long* g = (const long long*)gty;
        ci = (int)g[i]; cj = (int)g[j];
    } else {
        const int* g = (const int*)gty;
        ci = g[i]; cj = g[j];
    }
    if (ci != cj) return;
    int pos = atomicAdd(&g_count, 1);
    g_pairs[pos] = make_int2(i, j);
}

// ---------------------------------------------------------------------------
// 4) One warp per pair: sum_d (mu_i-mu_j)^2/(eps+sig_i+sig_j) + log(sig_sum)
//    2 MUFU ops per element; ln2 scale folded out of the loop.
// ---------------------------------------------------------------------------
__global__ void __launch_bounds__(CTHREADS)
mls_kernel() {
    int gw = (blockIdx.x * blockDim.x + threadIdx.x) >> 5;
    int lane = threadIdx.x & 31;
    int np = g_count;

    float accd = 0.0f;   // sum of d^2 * rcp(s)
    float accl = 0.0f;   // sum of lg2(s)

    for (int p = gw; p < np; p += NWARPS) {
        int2 pr = g_pairs[p];
        const float4* mi = (const float4*)(g_mu  + (size_t)pr.x * D);
        const float4* mj = (const float4*)(g_mu  + (size_t)pr.y * D);
        const float4* si = (const float4*)(g_sig + (size_t)pr.x * D);
        const float4* sj = (const float4*)(g_sig + (size_t)pr.y * D);
        #pragma unroll
        for (int k = 0; k < 4; k++) {
            int idx = lane + 32 * k;     // 128 float4 per row
            float4 a = mi[idx], b = mj[idx];
            float4 u = si[idx], v = sj[idx];
            float d, s;
            d = a.x - b.x; s = u.x + v.x + 1e-10f;
            accd += d * d * fast_rcp(s); accl += fast_lg2(s);
            d = a.y - b.y; s = u.y + v.y + 1e-10f;
            accd += d * d * fast_rcp(s); accl += fast_lg2(s);
            d = a.z - b.z; s = u.z + v.z + 1e-10f;
            accd += d * d * fast_rcp(s); accl += fast_lg2(s);
            d = a.w - b.w; s = u.w + v.w + 1e-10f;
            accd += d * d * fast_rcp(s); accl += fast_lg2(s);
        }
    }
    float val = accd + 0.69314718055994531f * accl;
    #pragma unroll
    for (int o = 16; o; o >>= 1) val += __shfl_xor_sync(0xFFFFFFFFu, val, o);
    if (lane == 0) g_partials[gw] = val;
}

// ---------------------------------------------------------------------------
// 5) Deterministic final reduction (double), divide by count, write scalar.
//    sum over i<j divided by count over i<j == masked mean over full matrix.
// ---------------------------------------------------------------------------
__global__ void finish_kernel(float* __restrict__ out) {
    __shared__ double sm[256];
    double acc = 0.0;
    for (int i = threadIdx.x; i < NWARPS; i += 256)
        acc += (double)g_partials[i];
    sm[threadIdx.x] = acc;
    __syncthreads();
    for (int s = 128; s; s >>= 1) {
        if (threadIdx.x < s) sm[threadIdx.x] += sm[threadIdx.x + s];
        __syncthreads();
    }
    if (threadIdx.x == 0) {
        int c = g_count;
        out[0] = c ? (float)(sm[0] / (double)c) : 0.0f;
    }
}

extern "C" void kernel_launch(void* const* d_in, const int* in_sizes, int n_in,
                              void* d_out, int out_size) {
    const float* muX = (const float*)d_in[0];
    const float* lss = (const float*)d_in[1];
    const void*  gty = d_in[2];
    (void)in_sizes; (void)n_in; (void)out_size;

    init_kernel<<<1, 768>>>(gty);
    prep_kernel<<<N, 128>>>(muX, lss);
    pairs_kernel<<<(N * N + 255) / 256, 256>>>(gty);
    mls_kernel<<<CBLOCKS, CTHREADS>>>();
    finish_kernel<<<1, 256>>>((float*)d_out);
}

// round 2
// speedup vs baseline: 1.2900x; 1.2900x over previous
#include <cuda_runtime.h>

#define N 768
#define D 512
#define NN (N * N)
#define B2 296
#define T2 256
#define TOT (B2 * T2)                     // 75776 threads in K2
#define STEPS ((NN + TOT - 1) / TOT)      // 8 candidate steps per thread
#define MAXLIST 2048                      // worst case: all candidates of one block match

// Scratch (no allocations allowed anywhere)
__device__ float  g_mu[N * D];
__device__ float  g_sig[N * D];
__device__ double g_sum;
__device__ int    g_cnt;
__device__ int    g_done;

__device__ __forceinline__ float fast_rcp(float x) {
    float r; asm("rcp.approx.f32 %0, %1;" : "=f"(r) : "f"(x)); return r;
}
__device__ __forceinline__ float fast_lg2(float x) {
    float r; asm("lg2.approx.f32 %0, %1;" : "=f"(r) : "f"(x)); return r;
}

// ---------------------------------------------------------------------------
// K1: per-row L2-normalize mu_X, sig = exp(log_sigma_sq). One block per row.
//     Block 0 also zeroes the cross-kernel accumulators for this replay.
// ---------------------------------------------------------------------------
__global__ void prep_kernel(const float* __restrict__ muX,
                            const float* __restrict__ lss) {
    if (blockIdx.x == 0 && threadIdx.x == 0) {
        g_sum = 0.0; g_cnt = 0; g_done = 0;
    }
    int row = blockIdx.x;
    int t = threadIdx.x;                  // 128 threads, 4 floats each
    const float4* src = (const float4*)(muX + (size_t)row * D);
    float4 v = src[t];
    float ss = v.x * v.x + v.y * v.y + v.z * v.z + v.w * v.w;
    #pragma unroll
    for (int o = 16; o; o >>= 1) ss += __shfl_xor_sync(0xFFFFFFFFu, ss, o);
    __shared__ float ws[4];
    if ((t & 31) == 0) ws[t >> 5] = ss;
    __syncthreads();
    float total = ws[0] + ws[1] + ws[2] + ws[3];
    float rn = 1.0f / fmaxf(sqrtf(total), 1e-12f);

    ((float4*)(g_mu + (size_t)row * D))[t] =
        make_float4(v.x * rn, v.y * rn, v.z * rn, v.w * rn);

    float4 l = ((const float4*)(lss + (size_t)row * D))[t];
    ((float4*)(g_sig + (size_t)row * D))[t] =
        make_float4(__expf(l.x), __expf(l.y), __expf(l.z), __expf(l.w));
}

// ---------------------------------------------------------------------------
// K2: fused filter + MLS + final reduction.
// ---------------------------------------------------------------------------
__global__ void __launch_bounds__(T2)
fused_kernel(const void* __restrict__ gty, float* __restrict__ out) {
    __shared__ int    lab[N];
    __shared__ int    sh_list[MAXLIST];
    __shared__ int    sh_n;
    __shared__ double wsum[T2 / 32];
    __shared__ int    wcnt[T2 / 32];

    int t = threadIdx.x;
    int lane = t & 31;
    int wid = t >> 5;

    // --- label load with in-block int64/int32 width detection ---
    // gty values are in [0,64). If stored as little-endian int64, every odd
    // 32-bit word of the first 768 words is 0. Reading 768 words is in-bounds
    // for both layouts.
    const int* gw = (const int*)gty;
    int flag = 0;
    for (int i = t; i < N; i += T2)
        if ((i & 1) && gw[i] != 0) flag = 1;
    if (t == 0) sh_n = 0;
    int is32 = __syncthreads_or(flag);
    for (int i = t; i < N; i += T2)
        lab[i] = is32 ? gw[i] : gw[2 * i];
    __syncthreads();

    // --- phase A: filter this block's candidate slice into shared list ---
    int gtid = blockIdx.x * T2 + t;
    #pragma unroll
    for (int s = 0; s < STEPS; s++) {
        int c = gtid + s * TOT;
        if (c < NN) {
            int i = c / N;
            int j = c - i * N;
            if (j > i && lab[i] == lab[j]) {
                int pos = atomicAdd(&sh_n, 1);
                sh_list[pos] = (i << 16) | j;
            }
        }
    }
    __syncthreads();
    int np = sh_n;

    // --- phase B: warps process the block's pair list round-robin ---
    float accd = 0.0f;   // sum of d^2 * rcp(s)
    float accl = 0.0f;   // sum of lg2(s)
    for (int p = wid; p < np; p += T2 / 32) {
        int pk = sh_list[p];
        int pi = pk >> 16;
        int pj = pk & 0xFFFF;
        const float4* mi = (const float4*)(g_mu  + (size_t)pi * D);
        const float4* mj = (const float4*)(g_mu  + (size_t)pj * D);
        const float4* si = (const float4*)(g_sig + (size_t)pi * D);
        const float4* sj = (const float4*)(g_sig + (size_t)pj * D);
        #pragma unroll
        for (int k = 0; k < 4; k++) {
            int idx = lane + 32 * k;      // 128 float4 per row
            float4 a = mi[idx], b = mj[idx];
            float4 u = si[idx], v = sj[idx];
            float d, sv;
            d = a.x - b.x; sv = u.x + v.x + 1e-10f;
            accd += d * d * fast_rcp(sv); accl += fast_lg2(sv);
            d = a.y - b.y; sv = u.y + v.y + 1e-10f;
            accd += d * d * fast_rcp(sv); accl += fast_lg2(sv);
            d = a.z - b.z; sv = u.z + v.z + 1e-10f;
            accd += d * d * fast_rcp(sv); accl += fast_lg2(sv);
            d = a.w - b.w; sv = u.w + v.w + 1e-10f;
            accd += d * d * fast_rcp(sv); accl += fast_lg2(sv);
        }
    }

    // --- reductions ---
    float val = accd + 0.69314718055994531f * accl;
    #pragma unroll
    for (int o = 16; o; o >>= 1) val += __shfl_xor_sync(0xFFFFFFFFu, val, o);
    if (lane == 0) { wsum[wid] = (double)val; wcnt[wid] = 0; }
    __syncthreads();
    if (t == 0) {
        double bs = 0.0;
        #pragma unroll
        for (int w = 0; w < T2 / 32; w++) bs += wsum[w];
        atomicAdd(&g_sum, bs);
        atomicAdd(&g_cnt, np);
        __threadfence();
        // last block computes the final scalar
        if (atomicAdd(&g_done, 1) == B2 - 1) {
            double s = atomicAdd(&g_sum, 0.0);   // coherent read
            int    c = atomicAdd(&g_cnt, 0);
            out[0] = c ? (float)(s / (double)c) : 0.0f;
        }
    }
}

extern "C" void kernel_launch(void* const* d_in, const int* in_sizes, int n_in,
                              void* d_out, int out_size) {
    const float* muX = (const float*)d_in[0];
    const float* lss = (const float*)d_in[1];
    const void*  gty = d_in[2];
    (void)in_sizes; (void)n_in; (void)out_size;

    prep_kernel<<<N, 128>>>(muX, lss);
    fused_kernel<<<B2, T2>>>(gty, (float*)d_out);
}

// round 3
// speedup vs baseline: 1.2949x; 1.0038x over previous
#include <cuda_runtime.h>

#define N 768
#define D 512
#define MAXP ((N * (N - 1)) / 2)
#define B2 888
#define T2 256
#define NW2 (B2 * T2 / 32)            // 7104 warps in K2

// Scratch (no allocations allowed anywhere)
__device__ float  g_mu[N * D];
__device__ float  g_sig[N * D];
__device__ int    g_pairs[MAXP];
__device__ double g_part[B2];
__device__ int    g_cnt;              // zero-init; reset by K2's last block
__device__ int    g_done;

__device__ __forceinline__ float fast_rcp(float x) {
    float r; asm("rcp.approx.f32 %0, %1;" : "=f"(r) : "f"(x)); return r;
}
__device__ __forceinline__ float fast_lg2(float x) {
    float r; asm("lg2.approx.f32 %0, %1;" : "=f"(r) : "f"(x)); return r;
}

// ---------------------------------------------------------------------------
// K1: per-row normalize + exp  AND  pair-list generation.
//     Block i: 128 threads. Also scans j in (i, N) for label matches and
//     appends (i,j) pairs with warp-aggregated atomics.
// ---------------------------------------------------------------------------
__global__ void __launch_bounds__(128)
prep_kernel(const float* __restrict__ muX,
            const float* __restrict__ lss,
            const void*  __restrict__ gty) {
    int i = blockIdx.x;
    int t = threadIdx.x;

    // ---- mu normalize + sig = exp ----
    float4 v = ((const float4*)(muX + (size_t)i * D))[t];
    float ss = v.x * v.x + v.y * v.y + v.z * v.z + v.w * v.w;
    #pragma unroll
    for (int o = 16; o; o >>= 1) ss += __shfl_xor_sync(0xFFFFFFFFu, ss, o);
    __shared__ float ws[4];
    if ((t & 31) == 0) ws[t >> 5] = ss;

    // ---- label width detection (int64 vs int32), overlapped with sync ----
    // Values are in [0,64). If int64 little-endian, odd 32-bit words of the
    // first N words are all 0. Reading N words is in-bounds either way.
    const int* gw = (const int*)gty;
    int flag = 0;
    #pragma unroll
    for (int k = 0; k < 6; k++) {
        int x = t + (k << 7);
        if ((x & 1) && gw[x] != 0) flag = 1;
    }
    int is32 = __syncthreads_or(flag);

    float total = ws[0] + ws[1] + ws[2] + ws[3];
    float rn = 1.0f / fmaxf(sqrtf(total), 1e-12f);
    ((float4*)(g_mu + (size_t)i * D))[t] =
        make_float4(v.x * rn, v.y * rn, v.z * rn, v.w * rn);
    float4 l = ((const float4*)(lss + (size_t)i * D))[t];
    ((float4*)(g_sig + (size_t)i * D))[t] =
        make_float4(__expf(l.x), __expf(l.y), __expf(l.z), __expf(l.w));

    // ---- pair generation: j = t + 128k, j > i, lab[j] == lab[i] ----
    int li = is32 ? gw[i] : gw[2 * i];
    #pragma unroll
    for (int k = 0; k < 6; k++) {
        int j = t + (k << 7);
        bool m = (j > i) && ((is32 ? gw[j] : gw[2 * j]) == li);
        unsigned bal = __ballot_sync(0xFFFFFFFFu, m);
        int cnt = __popc(bal);
        int base = 0;
        if ((t & 31) == 0 && cnt) base = atomicAdd(&g_cnt, cnt);
        base = __shfl_sync(0xFFFFFFFFu, base, 0);
        if (m) {
            int rank = __popc(bal & ((1u << (t & 31)) - 1));
            g_pairs[base + rank] = (i << 16) | j;
        }
    }
}

// ---------------------------------------------------------------------------
// K2: MLS over (pair, quarter) units; last-done block reduces + resets.
// ---------------------------------------------------------------------------
__global__ void __launch_bounds__(T2)
mls_kernel(float* __restrict__ out) {
    __shared__ double wsum[T2 / 32];
    __shared__ int    sh_last;

    int t = threadIdx.x;
    int lane = t & 31;
    int wid = t >> 5;
    int gw = blockIdx.x * (T2 / 32) + wid;

    int np = g_cnt;
    int nu = np << 2;                 // 4 quarter-units per pair

    float accd = 0.0f, accl = 0.0f;
    for (int u = gw; u < nu; u += NW2) {
        int pk = g_pairs[u >> 2];
        int pi = pk >> 16;
        int pj = pk & 0xFFFF;
        int f4 = ((u & 3) << 5) + lane;   // float4 index within row (0..127)
        float4 a  = ((const float4*)(g_mu  + (size_t)pi * D))[f4];
        float4 b  = ((const float4*)(g_mu  + (size_t)pj * D))[f4];
        float4 uu = ((const float4*)(g_sig + (size_t)pi * D))[f4];
        float4 vv = ((const float4*)(g_sig + (size_t)pj * D))[f4];
        float d, s;
        d = a.x - b.x; s = uu.x + vv.x + 1e-10f;
        accd += d * d * fast_rcp(s); accl += fast_lg2(s);
        d = a.y - b.y; s = uu.y + vv.y + 1e-10f;
        accd += d * d * fast_rcp(s); accl += fast_lg2(s);
        d = a.z - b.z; s = uu.z + vv.z + 1e-10f;
        accd += d * d * fast_rcp(s); accl += fast_lg2(s);
        d = a.w - b.w; s = uu.w + vv.w + 1e-10f;
        accd += d * d * fast_rcp(s); accl += fast_lg2(s);
    }

    // warp reduce (float), then block reduce (double)
    float val = accd + 0.69314718055994531f * accl;
    #pragma unroll
    for (int o = 16; o; o >>= 1) val += __shfl_xor_sync(0xFFFFFFFFu, val, o);
    if (lane == 0) wsum[wid] = (double)val;
    __syncthreads();
    if (t == 0) {
        double bs = 0.0;
        #pragma unroll
        for (int w = 0; w < T2 / 32; w++) bs += wsum[w];
        g_part[blockIdx.x] = bs;
        __threadfence();
        sh_last = (atomicAdd(&g_done, 1) == B2 - 1) ? 1 : 0;
    }
    __syncthreads();

    // last block: final reduction over all block partials, write scalar, reset
    if (sh_last) {
        double a2 = 0.0;
        for (int i = t; i < B2; i += T2)
            a2 += __ldcg(&g_part[i]);        // bypass L1 (other SMs wrote these)
        #pragma unroll
        for (int o = 16; o; o >>= 1) a2 += __shfl_xor_sync(0xFFFFFFFFu, a2, o);
        if (lane == 0) wsum[wid] = a2;
        __syncthreads();
        if (t == 0) {
            double s = 0.0;
            #pragma unroll
            for (int w = 0; w < T2 / 32; w++) s += wsum[w];
            out[0] = np ? (float)(s / (double)np) : 0.0f;
            g_done = 0;                       // reset for next graph replay
            g_cnt = 0;
        }
    }
}

extern "C" void kernel_launch(void* const* d_in, const int* in_sizes, int n_in,
                              void* d_out, int out_size) {
    const float* muX = (const float*)d_in[0];
    const float* lss = (const float*)d_in[1];
    const void*  gty = d_in[2];
    (void)in_sizes; (void)n_in; (void)out_size;

    prep_kernel<<<N, 128>>>(muX, lss, gty);
    mls_kernel<<<B2, T2>>>((float*)d_out);
}

// round 4
// speedup vs baseline: 1.3198x; 1.0193x over previous
#include <cuda_runtime.h>

#define N 768
#define D 512
#define MAXP ((N * (N - 1)) / 2)
#define NB 384
#define NT 256
#define NWARP (NB * NT / 32)          // 3072 warps

// Scratch (no allocations allowed anywhere). Zero-initialized at load.
__device__ float  g_mu[N * D];
__device__ float  g_sig[N * D];
__device__ int    g_pairs[MAXP];
__device__ double g_part[NB];
__device__ int    g_cnt;              // pair count; reset by last-done block
__device__ int    g_arrive;           // grid barrier (ticketed, replay-safe)
__device__ int    g_done;

__device__ __forceinline__ float fast_rcp(float x) {
    float r; asm("rcp.approx.f32 %0, %1;" : "=f"(r) : "f"(x)); return r;
}
__device__ __forceinline__ float fast_lg2(float x) {
    float r; asm("lg2.approx.f32 %0, %1;" : "=f"(r) : "f"(x)); return r;
}

__global__ void __launch_bounds__(NT)
mls_fused(const float* __restrict__ muX,
          const float* __restrict__ lss,
          const void*  __restrict__ gty,
          float* __restrict__ out) {
    __shared__ float  ws[8];
    __shared__ double wsum[NT / 32];
    __shared__ int    s_go;

    int t    = threadIdx.x;
    int lane = t & 31;
    int wid  = t >> 5;
    int half = t >> 7;                // 0/1: which of the block's two rows
    int ht   = t & 127;               // thread index within the half
    int row  = (blockIdx.x << 1) + half;

    // ================= PHASE A: prep + pair generation ====================
    // Row sum-of-squares (warps 0-3 -> row0, warps 4-7 -> row1)
    float4 v = ((const float4*)(muX + (size_t)row * D))[ht];
    float ss = v.x * v.x + v.y * v.y + v.z * v.z + v.w * v.w;
    #pragma unroll
    for (int o = 16; o; o >>= 1) ss += __shfl_xor_sync(0xFFFFFFFFu, ss, o);
    if (lane == 0) ws[wid] = ss;

    // Label width detection: gty values in [0,64). If little-endian int64,
    // every odd 32-bit word of the first N words is 0. Reading N int32 words
    // (and later word 2*j <= 1534) is in-bounds for both layouts.
    const int* gw = (const int*)gty;
    int flag = 0;
    #pragma unroll
    for (int k = 0; k < 3; k++) {
        int x = t + (k << 8);
        if ((x & 1) && gw[x] != 0) flag = 1;
    }
    int is32 = __syncthreads_or(flag);

    float total = ws[half * 4] + ws[half * 4 + 1] +
                  ws[half * 4 + 2] + ws[half * 4 + 3];
    float rn = 1.0f / fmaxf(sqrtf(total), 1e-12f);
    ((float4*)(g_mu + (size_t)row * D))[ht] =
        make_float4(v.x * rn, v.y * rn, v.z * rn, v.w * rn);
    float4 l = ((const float4*)(lss + (size_t)row * D))[ht];
    ((float4*)(g_sig + (size_t)row * D))[ht] =
        make_float4(__expf(l.x), __expf(l.y), __expf(l.z), __expf(l.w));

    // Pair generation for this half's row: scan all j, keep j>row & same label
    int li = is32 ? gw[row] : gw[2 * row];
    #pragma unroll
    for (int k = 0; k < 6; k++) {
        int j = ht + (k << 7);
        bool m = (j > row) && ((is32 ? gw[j] : gw[2 * j]) == li);
        unsigned bal = __ballot_sync(0xFFFFFFFFu, m);
        int cnt = __popc(bal);
        int base = 0;
        if (lane == 0 && cnt) base = atomicAdd(&g_cnt, cnt);
        base = __shfl_sync(0xFFFFFFFFu, base, 0);
        if (m) g_pairs[base + __popc(bal & ((1u << lane) - 1))] = (row << 16) | j;
    }

    // ================= grid barrier (replay-safe ticketed) ================
    if (t == 0) {
        __threadfence();                               // release phase-A writes
        int ticket = atomicAdd(&g_arrive, 1);
        int target = (ticket / NB + 1) * NB;           // works even w/o reset
        while (atomicAdd(&g_arrive, 0) < target) __nanosleep(40);
        s_go = 1;
    }
    __syncthreads();
    __threadfence();   // acquire: flush L1D so phase-B loads see remote writes
    (void)s_go;

    // ================= PHASE B: MLS over (pair, quarter) units ============
    int np = g_cnt;
    int nu = np << 2;
    int gwarp = blockIdx.x * (NT / 32) + wid;

    float accd = 0.0f, accl = 0.0f;
    for (int u = gwarp; u < nu; u += NWARP) {
        int pk = g_pairs[u >> 2];
        int pi = pk >> 16;
        int pj = pk & 0xFFFF;
        int f4 = ((u & 3) << 5) + lane;               // float4 index (0..127)
        float4 a  = ((const float4*)(g_mu  + (size_t)pi * D))[f4];
        float4 b  = ((const float4*)(g_mu  + (size_t)pj * D))[f4];
        float4 uu = ((const float4*)(g_sig + (size_t)pi * D))[f4];
        float4 vv = ((const float4*)(g_sig + (size_t)pj * D))[f4];
        float d, s;
        d = a.x - b.x; s = uu.x + vv.x + 1e-10f;
        accd += d * d * fast_rcp(s); accl += fast_lg2(s);
        d = a.y - b.y; s = uu.y + vv.y + 1e-10f;
        accd += d * d * fast_rcp(s); accl += fast_lg2(s);
        d = a.z - b.z; s = uu.z + vv.z + 1e-10f;
        accd += d * d * fast_rcp(s); accl += fast_lg2(s);
        d = a.w - b.w; s = uu.w + vv.w + 1e-10f;
        accd += d * d * fast_rcp(s); accl += fast_lg2(s);
    }

    // warp reduce (float) then block reduce (double)
    float val = accd + 0.69314718055994531f * accl;
    #pragma unroll
    for (int o = 16; o; o >>= 1) val += __shfl_xor_sync(0xFFFFFFFFu, val, o);
    if (lane == 0) wsum[wid] = (double)val;
    __syncthreads();

    __shared__ int sh_last;
    if (t == 0) {
        double bs = 0.0;
        #pragma unroll
        for (int w = 0; w < NT / 32; w++) bs += wsum[w];
        g_part[blockIdx.x] = bs;
        __threadfence();
        sh_last = (atomicAdd(&g_done, 1) == NB - 1) ? 1 : 0;
    }
    __syncthreads();

    // last-done block: deterministic final reduction + counter reset
    if (sh_last) {
        double a2 = 0.0;
        for (int i = t; i < NB; i += NT)
            a2 += __ldcg(&g_part[i]);
        #pragma unroll
        for (int o = 16; o; o >>= 1) a2 += __shfl_xor_sync(0xFFFFFFFFu, a2, o);
        if (lane == 0) wsum[wid] = a2;
        __syncthreads();
        if (t == 0) {
            double s = 0.0;
            #pragma unroll
            for (int w = 0; w < NT / 32; w++) s += wsum[w];
            out[0] = np ? (float)(s / (double)np) : 0.0f;
            g_done = 0;                // reset for next graph replay
            g_cnt = 0;
            g_arrive = 0;              // all blocks are past the barrier here
        }
    }
}

extern "C" void kernel_launch(void* const* d_in, const int* in_sizes, int n_in,
                              void* d_out, int out_size) {
    const float* muX = (const float*)d_in[0];
    const float* lss = (const float*)d_in[1];
    const void*  gty = d_in[2];
    (void)in_sizes; (void)n_in; (void)out_size;

    mls_fused<<<NB, NT>>>(muX, lss, gty, (float*)d_out);
}